// round 15
// baseline (speedup 1.0000x reference)
#include <cuda_runtime.h>
#include <cuda_bf16.h>

// NeRF render + accumulate, bit-matching XLA:CPU's ReduceWindowRewriter
// (base_length=16) radix-16 cumsum tree. PASSES @ rel_err 1.5e-7.
// R12 = R11 champion (82.4us) + three individually-validated pieces:
//   - k2 fused into k1 (R10 k1, numerics proven)
//   - k4b precomputes l1s (scanned l1, exact k4 bracketing; numerics proven)
//   - k5 keeps R11's spill-free named-register groups, prefix = ONE coalesced
//     l1s[r-1] load (no per-thread l1 gather fold); stores excl instead of c
//     (bit-identical to k6's fsub(ci,s), which is dropped in k6).
// Rounding-critical sequences unchanged:
//   sdt_i = fmul(sigma_i, fsub(te_i, ts_i))
//   fold-left rows with fadd; c = (row0) ? acc : fadd(acc, prefix)
//   excl = fsub(c, sdt); d = fsub(excl_i, e_lead); w = fmul(exp(-d), 1-exp(-sdt))

#define MAX_S    (1 << 22)
#define N1_MAX   (MAX_S / 16)      // 262144
#define N2_MAX   (N1_MAX / 16)     // 16384
#define MAX_RAYS (1 << 18)
#define WARPS_PER_BLOCK 8
#define K6_THREADS (WARPS_PER_BLOCK * 32)

__device__ __align__(16) float g_sdt[MAX_S];
__device__ __align__(16) float g_e[MAX_S];       // excl_i = fsub(c_i, sdt_i)
__device__ __align__(16) float g_l1[N1_MAX];
__device__ __align__(16) float g_l1s[N1_MAX];    // scanned l1 (k4 bracketing)
__device__ __align__(16) float g_l2[N2_MAX];     // raw row totals of l1
__device__ __align__(16) float g_l2s[N2_MAX];    // scanned l2
__device__ int   g_rs[MAX_RAYS];
__device__ int   g_re[MAX_RAYS];
__device__ float g_elead[MAX_RAYS];

// ---------------------------------------------------------------------------
// K1: sdt = fmul(sg, fsub(te, ts)); fold-left per 16-row -> g_l1; then the
// block's 256 l1 values are folded (16 at a time, old-k2 fold-left order)
// into g_l2. Trailing zeros are inert (all sdt >= 0, fadd(x,+0)==x bitwise).
// Also zero-inits ray bounds. (R10 k1, numerics proven.)
// ---------------------------------------------------------------------------
__global__ __launch_bounds__(256)
void k1_sdt_fold(const float* __restrict__ ts,
                 const float* __restrict__ te,
                 const float* __restrict__ sg,
                 int S, int n_rays)
{
    __shared__ float sm[256];
    const int tid = threadIdx.x;
    const int r = blockIdx.x * 256 + tid;
    const int R = (S + 15) >> 4;

    for (int j = r; j < n_rays; j += gridDim.x * blockDim.x) { g_rs[j] = 0; g_re[j] = 0; }

    float acc = 0.0f;
    if (r < R) {
        const int base = r << 4;
        if (base + 16 <= S) {
            const float4* ts4 = reinterpret_cast<const float4*>(ts + base);
            const float4* te4 = reinterpret_cast<const float4*>(te + base);
            const float4* sg4 = reinterpret_cast<const float4*>(sg + base);
            float4*       sd4 = reinterpret_cast<float4*>(g_sdt + base);
            #pragma unroll
            for (int q = 0; q < 4; q++) {
                const float4 a = ts4[q], b = te4[q], s = sg4[q];
                float4 v;
                v.x = __fmul_rn(s.x, __fsub_rn(b.x, a.x));
                v.y = __fmul_rn(s.y, __fsub_rn(b.y, a.y));
                v.z = __fmul_rn(s.z, __fsub_rn(b.z, a.z));
                v.w = __fmul_rn(s.w, __fsub_rn(b.w, a.w));
                sd4[q] = v;
                acc = __fadd_rn(acc, v.x);   // exact fold-left order preserved
                acc = __fadd_rn(acc, v.y);
                acc = __fadd_rn(acc, v.z);
                acc = __fadd_rn(acc, v.w);
            }
        } else {
            const int lim = S - base;
            for (int k = 0; k < lim; k++) {
                const int i = base + k;
                const float v = __fmul_rn(sg[i], __fsub_rn(te[i], ts[i]));
                g_sdt[i] = v;
                acc = __fadd_rn(acc, v);
            }
        }
        g_l1[r] = acc;
    }

    sm[tid] = acc;               // acc==0 for inactive threads (inert)
    __syncthreads();
    if (tid < 16) {
        const int rowb = tid << 4;
        float a2 = 0.0f;
        #pragma unroll
        for (int k = 0; k < 16; k++)
            a2 = __fadd_rn(a2, sm[rowb + k]);
        g_l2[blockIdx.x * 16 + tid] = a2;
    }
}

// ---------------------------------------------------------------------------
// K3: single-CTA exact radix-16 scan: out = cum(in), n <= 16384. (R7.)
// ---------------------------------------------------------------------------
__device__ __forceinline__ void seq_scan(float* a, int n) {
    float acc = 0.0f;
    for (int i = 0; i < n; i++) { acc = __fadd_rn(acc, a[i]); a[i] = acc; }
}

__global__ __launch_bounds__(1024)
void k3_midscan(const float* __restrict__ in, float* __restrict__ out, int n)
{
    __shared__ float b1[1024], b2[64], b3[4];
    const int tid = threadIdx.x;

    if (n <= 16) {
        if (tid == 0) {
            float acc = 0.0f;
            for (int i = 0; i < n; i++) { acc = __fadd_rn(acc, in[i]); out[i] = acc; }
        }
        return;
    }

    const int m1 = (n + 15) >> 4;
    for (int q = tid; q < m1; q += 1024) {
        const int base = q << 4, lim = min(16, n - base);
        float acc = 0.0f;
        if (lim == 16) {
            const float4* in4 = reinterpret_cast<const float4*>(in + base);
            #pragma unroll
            for (int t = 0; t < 4; t++) {
                const float4 v = in4[t];
                acc = __fadd_rn(acc, v.x); acc = __fadd_rn(acc, v.y);
                acc = __fadd_rn(acc, v.z); acc = __fadd_rn(acc, v.w);
            }
        } else {
            for (int k = 0; k < lim; k++) acc = __fadd_rn(acc, in[base + k]);
        }
        b1[q] = acc;
    }
    __syncthreads();

    if (m1 <= 16) {
        if (tid == 0) seq_scan(b1, m1);
        __syncthreads();
    } else {
        const int m2 = (m1 + 15) >> 4;
        if (tid < m2) {
            const int base = tid << 4, lim = min(16, m1 - base);
            float acc = 0.0f;
            for (int k = 0; k < lim; k++) acc = __fadd_rn(acc, b1[base + k]);
            b2[tid] = acc;
        }
        __syncthreads();
        if (m2 <= 16) {
            if (tid == 0) seq_scan(b2, m2);
            __syncthreads();
        } else {
            const int m3 = (m2 + 15) >> 4;      // <= 4
            if (tid < m3) {
                const int base = tid << 4, lim = min(16, m2 - base);
                float acc = 0.0f;
                for (int k = 0; k < lim; k++) acc = __fadd_rn(acc, b2[base + k]);
                b3[tid] = acc;
            }
            __syncthreads();
            if (tid == 0) seq_scan(b3, m3);
            __syncthreads();
            if (tid < m3) {
                const int base = tid << 4, lim = min(16, m2 - base);
                float acc = 0.0f;
                const float p = (tid > 0) ? b3[tid - 1] : 0.0f;
                for (int k = 0; k < lim; k++) {
                    acc = __fadd_rn(acc, b2[base + k]);
                    b2[base + k] = (tid == 0) ? acc : __fadd_rn(acc, p);
                }
            }
            __syncthreads();
        }
        if (tid < m2) {
            const int base = tid << 4, lim = min(16, m1 - base);
            float acc = 0.0f;
            const float p = (tid > 0) ? b2[tid - 1] : 0.0f;
            for (int k = 0; k < lim; k++) {
                acc = __fadd_rn(acc, b1[base + k]);
                b1[base + k] = (tid == 0) ? acc : __fadd_rn(acc, p);
            }
        }
        __syncthreads();
    }
    for (int q = tid; q < m1; q += 1024) {
        const int base = q << 4, lim = min(16, n - base);
        float acc = 0.0f;
        const float p = (q > 0) ? b1[q - 1] : 0.0f;
        for (int k = 0; k < lim; k++) {
            acc = __fadd_rn(acc, in[base + k]);
            out[base + k] = (q == 0) ? acc : __fadd_rn(acc, p);
        }
    }
}

// ---------------------------------------------------------------------------
// K4b: l1s[r] = foldleft(l1[16q .. r]) (+ l2s[q-1] if q>0) — exact k4
// bracketing; small kernel, smem fold, no spills. (R10, numerics proven.)
// ---------------------------------------------------------------------------
__global__ __launch_bounds__(256)
void k4b_scan_l1(int n1)
{
    __shared__ float sm[256];
    const int tid = threadIdx.x;
    const int r = blockIdx.x * 256 + tid;
    sm[tid] = (r < n1) ? g_l1[r] : 0.0f;
    __syncthreads();
    if (r >= n1) return;
    const int q = r >> 4;
    const int j = r & 15;
    const int rowlocal = tid & ~15;
    float acc = 0.0f;
    for (int k = 0; k <= j; k++)
        acc = __fadd_rn(acc, sm[rowlocal + k]);
    g_l1s[r] = (q == 0) ? acc : __fadd_rn(acc, __ldg(g_l2s + q - 1));
}

// ---------------------------------------------------------------------------
// K5: final downsweep — spill-free named-register groups (R11-proven),
// prefix p = one coalesced l1s[r-1] load. Stores excl = fsub(cv, sd)
// (bit-identical to k6's old fsub(ci, s)). Bounds + per-ray e_lead.
// ---------------------------------------------------------------------------
__device__ __forceinline__ void k5_group(const float4 s, const int4 d, const int i0,
                                         const bool r0, const float p,
                                         float& acc, int& prev, float4& ev)
{
    float4 cv;
    acc = __fadd_rn(acc, s.x); cv.x = r0 ? acc : __fadd_rn(acc, p);
    acc = __fadd_rn(acc, s.y); cv.y = r0 ? acc : __fadd_rn(acc, p);
    acc = __fadd_rn(acc, s.z); cv.z = r0 ? acc : __fadd_rn(acc, p);
    acc = __fadd_rn(acc, s.w); cv.w = r0 ? acc : __fadd_rn(acc, p);

    ev.x = __fsub_rn(cv.x, s.x);
    ev.y = __fsub_rn(cv.y, s.y);
    ev.z = __fsub_rn(cv.z, s.z);
    ev.w = __fsub_rn(cv.w, s.w);

    if (d.x != prev) { g_rs[d.x] = i0;     if (prev >= 0) g_re[prev] = i0;     g_elead[d.x] = ev.x; }
    prev = d.x;
    if (d.y != prev) { g_rs[d.y] = i0 + 1; g_re[prev] = i0 + 1; g_elead[d.y] = ev.y; }
    prev = d.y;
    if (d.z != prev) { g_rs[d.z] = i0 + 2; g_re[prev] = i0 + 2; g_elead[d.z] = ev.z; }
    prev = d.z;
    if (d.w != prev) { g_rs[d.w] = i0 + 3; g_re[prev] = i0 + 3; g_elead[d.w] = ev.w; }
    prev = d.w;
}

__global__ __launch_bounds__(256)
void k5_down0_bounds(const int* __restrict__ idx, int S)
{
    const int r = blockIdx.x * blockDim.x + threadIdx.x;
    const int R = (S + 15) >> 4;
    if (r >= R) return;
    const int base = r << 4;
    const int lim  = min(16, S - base);

    const float p = (r > 0) ? __ldg(g_l1s + r - 1) : 0.0f;
    int prev = (base > 0) ? __ldg(idx + base - 1) : -1;
    const bool r0 = (r == 0);

    if (lim == 16) {
        const float4* sd4 = reinterpret_cast<const float4*>(g_sdt + base);
        const int4*   id4 = reinterpret_cast<const int4*>(idx + base);
        const float4 s0 = sd4[0], s1 = sd4[1], s2 = sd4[2], s3 = sd4[3];
        const int4   d0 = id4[0], d1 = id4[1], d2 = id4[2], d3 = id4[3];
        float4* e4 = reinterpret_cast<float4*>(g_e + base);

        float acc = 0.0f;
        float4 ev;
        k5_group(s0, d0, base +  0, r0, p, acc, prev, ev); e4[0] = ev;
        k5_group(s1, d1, base +  4, r0, p, acc, prev, ev); e4[1] = ev;
        k5_group(s2, d2, base +  8, r0, p, acc, prev, ev); e4[2] = ev;
        k5_group(s3, d3, base + 12, r0, p, acc, prev, ev); e4[3] = ev;

        if (base + 16 == S) g_re[prev] = S;
    } else {
        float acc = 0.0f;
        for (int k = 0; k < lim; k++) {
            const int i = base + k;
            const float s = g_sdt[i];
            acc = __fadd_rn(acc, s);
            const float c = r0 ? acc : __fadd_rn(acc, p);
            const float e = __fsub_rn(c, s);
            g_e[i] = e;
            const int cur = idx[i];
            if (cur != prev) {
                g_rs[cur] = i;
                if (prev >= 0) g_re[prev] = i;
                g_elead[cur] = e;
            }
            prev = cur;
        }
        g_re[prev] = S;
    }
}

// ---------------------------------------------------------------------------
// K6: warp-per-ray render + accumulate (R7/R11 structure; reads excl array,
// one fewer fsub per sample).
// ---------------------------------------------------------------------------
__global__ __launch_bounds__(K6_THREADS)
void k6_render(const float* __restrict__ hdr,
               float*       __restrict__ out,
               int n_rays)
{
    const int r    = blockIdx.x * WARPS_PER_BLOCK + (threadIdx.x >> 5);
    const int lane = threadIdx.x & 31;
    if (r >= n_rays) return;

    int b = 0;
    float el = 0.0f;
    if (lane == 0)      { b = g_rs[r]; el = g_elead[r]; }
    else if (lane == 1)   b = g_re[r];
    const int start = __shfl_sync(0xffffffffu, b, 0);
    const int end   = __shfl_sync(0xffffffffu, b, 1);

    if (end <= start) {
        if (lane == 0)
            reinterpret_cast<float4*>(out)[r] = make_float4(0.f, 0.f, 0.f, 0.f);
        return;
    }
    const float e_lead = __shfl_sync(0xffffffffu, el, 0);

    float opac = 0.0f, cr = 0.0f, cg = 0.0f, cb = 0.0f;

    for (int base = start; base < end; base += 32) {
        const int i = base + lane;
        if (i < end) {
            const float s  = __ldg(g_sdt + i);
            const float ei = __ldg(g_e + i);
            const float d  = __fsub_rn(ei, e_lead);
            const float trans = expf(-d);
            const float alpha = 1.0f - expf(-s);
            const float w = __fmul_rn(trans, alpha);
            const long hoff = 3l * i;
            opac += w;
            cr += w * __ldg(hdr + hoff + 0);
            cg += w * __ldg(hdr + hoff + 1);
            cb += w * __ldg(hdr + hoff + 2);
        }
    }

    #pragma unroll
    for (int o = 16; o > 0; o >>= 1) {
        opac += __shfl_xor_sync(0xffffffffu, opac, o);
        cr   += __shfl_xor_sync(0xffffffffu, cr,   o);
        cg   += __shfl_xor_sync(0xffffffffu, cg,   o);
        cb   += __shfl_xor_sync(0xffffffffu, cb,   o);
    }

    if (lane == 0)
        reinterpret_cast<float4*>(out)[r] = make_float4(opac, cr, cg, cb);
}

// ---------------------------------------------------------------------------
extern "C" void kernel_launch(void* const* d_in, const int* in_sizes, int n_in,
                              void* d_out, int out_size)
{
    const float* t_starts    = (const float*)d_in[0];
    const float* t_ends      = (const float*)d_in[1];
    const float* sigmas      = (const float*)d_in[2];
    const float* hdr         = (const float*)d_in[3];
    const int*   ray_indices = (const int*)  d_in[4];
    float*       out         = (float*)d_out;

    const int S      = in_sizes[0];
    const int n_rays = out_size / 4;

    const int n1 = (S + 15) >> 4;
    const int n2 = (n1 + 15) >> 4;

    float *l2 = nullptr, *l2s = nullptr;
    cudaGetSymbolAddress((void**)&l2,  g_l2);
    cudaGetSymbolAddress((void**)&l2s, g_l2s);

    const int T = 256;
    const int g1 = (n1 + T - 1) / T;

    k1_sdt_fold<<<g1, T>>>(t_starts, t_ends, sigmas, S, n_rays);
    k3_midscan<<<1, 1024>>>(l2, l2s, n2);
    k4b_scan_l1<<<g1, T>>>(n1);
    k5_down0_bounds<<<g1, T>>>(ray_indices, S);

    const int blocks = (n_rays + WARPS_PER_BLOCK - 1) / WARPS_PER_BLOCK;
    k6_render<<<blocks, K6_THREADS>>>(hdr, out, n_rays);
}

// round 16
// speedup vs baseline: 1.0338x; 1.0338x over previous
#include <cuda_runtime.h>
#include <cuda_bf16.h>

// NeRF render + accumulate, bit-matching XLA:CPU's ReduceWindowRewriter
// (base_length=16) radix-16 cumsum tree. PASSES @ rel_err 1.5e-7.
// R15: k6 rewritten sample-centric — thread-per-sample streaming, warp-
// segmented Kogge-Stone partial sums, one atomicAdd set per segment-last
// lane. k5 drops rs/re bookkeeping (only e_lead per ray needed now).
// k1 zero-inits the output (poisoned 0xAA; empty rays must be 0).
// Rounding-critical per-sample sequences unchanged:
//   sdt_i = fmul(sigma_i, fsub(te_i, ts_i))
//   fold-left rows with fadd; c = (row0) ? acc : fadd(acc, prefix)
//   excl = fsub(c, sdt); d = fsub(excl_i, e_lead); w = fmul(exp(-d), 1-exp(-sdt))

#define MAX_S    (1 << 22)
#define N1_MAX   (MAX_S / 16)      // 262144
#define N2_MAX   (N1_MAX / 16)     // 16384
#define MAX_RAYS (1 << 18)

__device__ __align__(16) float g_sdt[MAX_S];
__device__ __align__(16) float g_e[MAX_S];       // excl_i = fsub(c_i, sdt_i)
__device__ __align__(16) float g_l1[N1_MAX];
__device__ __align__(16) float g_l1s[N1_MAX];    // scanned l1 (k4 bracketing)
__device__ __align__(16) float g_l2[N2_MAX];     // raw row totals of l1
__device__ __align__(16) float g_l2s[N2_MAX];    // scanned l2
__device__ float g_elead[MAX_RAYS];

// ---------------------------------------------------------------------------
// K1: sdt = fmul(sg, fsub(te, ts)); fold-left per 16-row -> g_l1; block's
// 256 l1 values folded (16-wide, old-k2 fold-left order) -> g_l2.
// Also zero-inits the output (one float4 per ray).
// ---------------------------------------------------------------------------
__global__ __launch_bounds__(256)
void k1_sdt_fold(const float* __restrict__ ts,
                 const float* __restrict__ te,
                 const float* __restrict__ sg,
                 float* __restrict__ out,
                 int S, int n_rays)
{
    __shared__ float sm[256];
    const int tid = threadIdx.x;
    const int r = blockIdx.x * 256 + tid;
    const int R = (S + 15) >> 4;

    for (int j = r; j < n_rays; j += gridDim.x * blockDim.x)
        reinterpret_cast<float4*>(out)[j] = make_float4(0.f, 0.f, 0.f, 0.f);

    float acc = 0.0f;
    if (r < R) {
        const int base = r << 4;
        if (base + 16 <= S) {
            const float4* ts4 = reinterpret_cast<const float4*>(ts + base);
            const float4* te4 = reinterpret_cast<const float4*>(te + base);
            const float4* sg4 = reinterpret_cast<const float4*>(sg + base);
            float4*       sd4 = reinterpret_cast<float4*>(g_sdt + base);
            #pragma unroll
            for (int q = 0; q < 4; q++) {
                const float4 a = ts4[q], b = te4[q], s = sg4[q];
                float4 v;
                v.x = __fmul_rn(s.x, __fsub_rn(b.x, a.x));
                v.y = __fmul_rn(s.y, __fsub_rn(b.y, a.y));
                v.z = __fmul_rn(s.z, __fsub_rn(b.z, a.z));
                v.w = __fmul_rn(s.w, __fsub_rn(b.w, a.w));
                sd4[q] = v;
                acc = __fadd_rn(acc, v.x);   // exact fold-left order preserved
                acc = __fadd_rn(acc, v.y);
                acc = __fadd_rn(acc, v.z);
                acc = __fadd_rn(acc, v.w);
            }
        } else {
            const int lim = S - base;
            for (int k = 0; k < lim; k++) {
                const int i = base + k;
                const float v = __fmul_rn(sg[i], __fsub_rn(te[i], ts[i]));
                g_sdt[i] = v;
                acc = __fadd_rn(acc, v);
            }
        }
        g_l1[r] = acc;
    }

    sm[tid] = acc;               // acc==0 for inactive threads (inert: sdt>=0)
    __syncthreads();
    if (tid < 16) {
        const int rowb = tid << 4;
        float a2 = 0.0f;
        #pragma unroll
        for (int k = 0; k < 16; k++)
            a2 = __fadd_rn(a2, sm[rowb + k]);
        g_l2[blockIdx.x * 16 + tid] = a2;
    }
}

// ---------------------------------------------------------------------------
// K3: single-CTA exact radix-16 scan: out = cum(in), n <= 16384.
// ---------------------------------------------------------------------------
__device__ __forceinline__ void seq_scan(float* a, int n) {
    float acc = 0.0f;
    for (int i = 0; i < n; i++) { acc = __fadd_rn(acc, a[i]); a[i] = acc; }
}

__global__ __launch_bounds__(1024)
void k3_midscan(const float* __restrict__ in, float* __restrict__ out, int n)
{
    __shared__ float b1[1024], b2[64], b3[4];
    const int tid = threadIdx.x;

    if (n <= 16) {
        if (tid == 0) {
            float acc = 0.0f;
            for (int i = 0; i < n; i++) { acc = __fadd_rn(acc, in[i]); out[i] = acc; }
        }
        return;
    }

    const int m1 = (n + 15) >> 4;
    for (int q = tid; q < m1; q += 1024) {
        const int base = q << 4, lim = min(16, n - base);
        float acc = 0.0f;
        if (lim == 16) {
            const float4* in4 = reinterpret_cast<const float4*>(in + base);
            #pragma unroll
            for (int t = 0; t < 4; t++) {
                const float4 v = in4[t];
                acc = __fadd_rn(acc, v.x); acc = __fadd_rn(acc, v.y);
                acc = __fadd_rn(acc, v.z); acc = __fadd_rn(acc, v.w);
            }
        } else {
            for (int k = 0; k < lim; k++) acc = __fadd_rn(acc, in[base + k]);
        }
        b1[q] = acc;
    }
    __syncthreads();

    if (m1 <= 16) {
        if (tid == 0) seq_scan(b1, m1);
        __syncthreads();
    } else {
        const int m2 = (m1 + 15) >> 4;
        if (tid < m2) {
            const int base = tid << 4, lim = min(16, m1 - base);
            float acc = 0.0f;
            for (int k = 0; k < lim; k++) acc = __fadd_rn(acc, b1[base + k]);
            b2[tid] = acc;
        }
        __syncthreads();
        if (m2 <= 16) {
            if (tid == 0) seq_scan(b2, m2);
            __syncthreads();
        } else {
            const int m3 = (m2 + 15) >> 4;      // <= 4
            if (tid < m3) {
                const int base = tid << 4, lim = min(16, m2 - base);
                float acc = 0.0f;
                for (int k = 0; k < lim; k++) acc = __fadd_rn(acc, b2[base + k]);
                b3[tid] = acc;
            }
            __syncthreads();
            if (tid == 0) seq_scan(b3, m3);
            __syncthreads();
            if (tid < m3) {
                const int base = tid << 4, lim = min(16, m2 - base);
                float acc = 0.0f;
                const float p = (tid > 0) ? b3[tid - 1] : 0.0f;
                for (int k = 0; k < lim; k++) {
                    acc = __fadd_rn(acc, b2[base + k]);
                    b2[base + k] = (tid == 0) ? acc : __fadd_rn(acc, p);
                }
            }
            __syncthreads();
        }
        if (tid < m2) {
            const int base = tid << 4, lim = min(16, m1 - base);
            float acc = 0.0f;
            const float p = (tid > 0) ? b2[tid - 1] : 0.0f;
            for (int k = 0; k < lim; k++) {
                acc = __fadd_rn(acc, b1[base + k]);
                b1[base + k] = (tid == 0) ? acc : __fadd_rn(acc, p);
            }
        }
        __syncthreads();
    }
    for (int q = tid; q < m1; q += 1024) {
        const int base = q << 4, lim = min(16, n - base);
        float acc = 0.0f;
        const float p = (q > 0) ? b1[q - 1] : 0.0f;
        for (int k = 0; k < lim; k++) {
            acc = __fadd_rn(acc, in[base + k]);
            out[base + k] = (q == 0) ? acc : __fadd_rn(acc, p);
        }
    }
}

// ---------------------------------------------------------------------------
// K4b: l1s[r] = foldleft(l1[16q .. r]) (+ l2s[q-1] if q>0) — exact k4
// bracketing; small kernel, smem fold, no spills.
// ---------------------------------------------------------------------------
__global__ __launch_bounds__(256)
void k4b_scan_l1(int n1)
{
    __shared__ float sm[256];
    const int tid = threadIdx.x;
    const int r = blockIdx.x * 256 + tid;
    sm[tid] = (r < n1) ? g_l1[r] : 0.0f;
    __syncthreads();
    if (r >= n1) return;
    const int q = r >> 4;
    const int j = r & 15;
    const int rowlocal = tid & ~15;
    float acc = 0.0f;
    for (int k = 0; k <= j; k++)
        acc = __fadd_rn(acc, sm[rowlocal + k]);
    g_l1s[r] = (q == 0) ? acc : __fadd_rn(acc, __ldg(g_l2s + q - 1));
}

// ---------------------------------------------------------------------------
// K5: final downsweep — spill-free named-register groups, prefix p = one
// coalesced l1s[r-1] load. Stores excl = fsub(cv, sd) and per-ray e_lead at
// each segment start. (rs/re no longer needed by k6.)
// ---------------------------------------------------------------------------
__device__ __forceinline__ void k5_group(const float4 s, const int4 d,
                                         const bool r0, const float p,
                                         float& acc, int& prev, float4& ev)
{
    float4 cv;
    acc = __fadd_rn(acc, s.x); cv.x = r0 ? acc : __fadd_rn(acc, p);
    acc = __fadd_rn(acc, s.y); cv.y = r0 ? acc : __fadd_rn(acc, p);
    acc = __fadd_rn(acc, s.z); cv.z = r0 ? acc : __fadd_rn(acc, p);
    acc = __fadd_rn(acc, s.w); cv.w = r0 ? acc : __fadd_rn(acc, p);

    ev.x = __fsub_rn(cv.x, s.x);
    ev.y = __fsub_rn(cv.y, s.y);
    ev.z = __fsub_rn(cv.z, s.z);
    ev.w = __fsub_rn(cv.w, s.w);

    if (d.x != prev) g_elead[d.x] = ev.x;
    prev = d.x;
    if (d.y != prev) g_elead[d.y] = ev.y;
    prev = d.y;
    if (d.z != prev) g_elead[d.z] = ev.z;
    prev = d.z;
    if (d.w != prev) g_elead[d.w] = ev.w;
    prev = d.w;
}

__global__ __launch_bounds__(256)
void k5_down0_bounds(const int* __restrict__ idx, int S)
{
    const int r = blockIdx.x * blockDim.x + threadIdx.x;
    const int R = (S + 15) >> 4;
    if (r >= R) return;
    const int base = r << 4;
    const int lim  = min(16, S - base);

    const float p = (r > 0) ? __ldg(g_l1s + r - 1) : 0.0f;
    int prev = (base > 0) ? __ldg(idx + base - 1) : -1;
    const bool r0 = (r == 0);

    if (lim == 16) {
        const float4* sd4 = reinterpret_cast<const float4*>(g_sdt + base);
        const int4*   id4 = reinterpret_cast<const int4*>(idx + base);
        const float4 s0 = sd4[0], s1 = sd4[1], s2 = sd4[2], s3 = sd4[3];
        const int4   d0 = id4[0], d1 = id4[1], d2 = id4[2], d3 = id4[3];
        float4* e4 = reinterpret_cast<float4*>(g_e + base);

        float acc = 0.0f;
        float4 ev;
        k5_group(s0, d0, r0, p, acc, prev, ev); e4[0] = ev;
        k5_group(s1, d1, r0, p, acc, prev, ev); e4[1] = ev;
        k5_group(s2, d2, r0, p, acc, prev, ev); e4[2] = ev;
        k5_group(s3, d3, r0, p, acc, prev, ev); e4[3] = ev;
    } else {
        float acc = 0.0f;
        for (int k = 0; k < lim; k++) {
            const int i = base + k;
            const float s = g_sdt[i];
            acc = __fadd_rn(acc, s);
            const float c = r0 ? acc : __fadd_rn(acc, p);
            const float e = __fsub_rn(c, s);
            g_e[i] = e;
            const int cur = idx[i];
            if (cur != prev) g_elead[cur] = e;
            prev = cur;
        }
    }
}

// ---------------------------------------------------------------------------
// K6: sample-centric render — thread per sample, warp-segmented Kogge-Stone
// partial sums over the sorted ray ids, atomicAdd from segment-last lanes.
// Per-sample arithmetic sequence identical to previous k6.
// ---------------------------------------------------------------------------
__global__ __launch_bounds__(256)
void k6_render_seg(const int* __restrict__ idx,
                   const float* __restrict__ hdr,
                   float*       __restrict__ out,
                   int S)
{
    const int i    = blockIdx.x * 256 + threadIdx.x;
    const int lane = threadIdx.x & 31;

    int ray = -1;
    float opac = 0.0f, cr = 0.0f, cg = 0.0f, cb = 0.0f;

    if (i < S) {
        ray = __ldg(idx + i);
        const float s  = __ldg(g_sdt + i);
        const float ei = __ldg(g_e + i);
        const float el = __ldg(g_elead + ray);
        const float d  = __fsub_rn(ei, el);
        const float trans = expf(-d);
        const float alpha = 1.0f - expf(-s);
        const float w = __fmul_rn(trans, alpha);
        const long h = 3l * i;
        opac = w;
        cr = w * __ldg(hdr + h + 0);
        cg = w * __ldg(hdr + h + 1);
        cb = w * __ldg(hdr + h + 2);
    }

    // Segmented inclusive scan: merge from left neighbor while same ray.
    #pragma unroll
    for (int dlt = 1; dlt < 32; dlt <<= 1) {
        const int   oray = __shfl_up_sync(0xffffffffu, ray,  dlt);
        const float o0   = __shfl_up_sync(0xffffffffu, opac, dlt);
        const float o1   = __shfl_up_sync(0xffffffffu, cr,   dlt);
        const float o2   = __shfl_up_sync(0xffffffffu, cg,   dlt);
        const float o3   = __shfl_up_sync(0xffffffffu, cb,   dlt);
        if (lane >= dlt && oray == ray) {
            opac += o0; cr += o1; cg += o2; cb += o3;
        }
    }

    const int nray = __shfl_down_sync(0xffffffffu, ray, 1);
    const bool segend = (lane == 31) || (nray != ray);
    if (ray >= 0 && segend) {
        float* o = out + 4l * ray;
        atomicAdd(o + 0, opac);
        atomicAdd(o + 1, cr);
        atomicAdd(o + 2, cg);
        atomicAdd(o + 3, cb);
    }
}

// ---------------------------------------------------------------------------
extern "C" void kernel_launch(void* const* d_in, const int* in_sizes, int n_in,
                              void* d_out, int out_size)
{
    const float* t_starts    = (const float*)d_in[0];
    const float* t_ends      = (const float*)d_in[1];
    const float* sigmas      = (const float*)d_in[2];
    const float* hdr         = (const float*)d_in[3];
    const int*   ray_indices = (const int*)  d_in[4];
    float*       out         = (float*)d_out;

    const int S      = in_sizes[0];
    const int n_rays = out_size / 4;

    const int n1 = (S + 15) >> 4;
    const int n2 = (n1 + 15) >> 4;

    float *l2 = nullptr, *l2s = nullptr;
    cudaGetSymbolAddress((void**)&l2,  g_l2);
    cudaGetSymbolAddress((void**)&l2s, g_l2s);

    const int T = 256;
    const int g1 = (n1 + T - 1) / T;

    k1_sdt_fold<<<g1, T>>>(t_starts, t_ends, sigmas, out, S, n_rays);
    k3_midscan<<<1, 1024>>>(l2, l2s, n2);
    k4b_scan_l1<<<g1, T>>>(n1);
    k5_down0_bounds<<<g1, T>>>(ray_indices, S);

    const int g6 = (S + T - 1) / T;
    k6_render_seg<<<g6, T>>>(ray_indices, hdr, out, S);
}

// round 17
// speedup vs baseline: 1.1995x; 1.1603x over previous
#include <cuda_runtime.h>
#include <cuda_bf16.h>

// NeRF render + accumulate, bit-matching XLA:CPU's ReduceWindowRewriter
// (base_length=16) radix-16 cumsum tree. PASSES @ rel_err ~1.5e-7.
// R16: k6 rewritten pack-centric (4 samples/thread, fully vectorized loads,
// segmented Kogge-Stone over pack aggregates, atomic flush per run part).
// k1/k3/k4b/k5 identical to the R15 champion (81.3us).
// Rounding-critical per-sample sequences unchanged:
//   sdt_i = fmul(sigma_i, fsub(te_i, ts_i))
//   fold-left rows with fadd; c = (row0) ? acc : fadd(acc, prefix)
//   excl = fsub(c, sdt); d = fsub(excl_i, e_lead); w = fmul(exp(-d), 1-exp(-sdt))

#define MAX_S    (1 << 22)
#define N1_MAX   (MAX_S / 16)      // 262144
#define N2_MAX   (N1_MAX / 16)     // 16384
#define MAX_RAYS (1 << 18)

__device__ __align__(16) float g_sdt[MAX_S];
__device__ __align__(16) float g_e[MAX_S];       // excl_i = fsub(c_i, sdt_i)
__device__ __align__(16) float g_l1[N1_MAX];
__device__ __align__(16) float g_l1s[N1_MAX];    // scanned l1 (k4 bracketing)
__device__ __align__(16) float g_l2[N2_MAX];     // raw row totals of l1
__device__ __align__(16) float g_l2s[N2_MAX];    // scanned l2
__device__ float g_elead[MAX_RAYS];

// ---------------------------------------------------------------------------
// K1: sdt = fmul(sg, fsub(te, ts)); fold-left per 16-row -> g_l1; block's
// 256 l1 values folded (16-wide, old-k2 fold-left order) -> g_l2.
// Also zero-inits the output (one float4 per ray).
// ---------------------------------------------------------------------------
__global__ __launch_bounds__(256)
void k1_sdt_fold(const float* __restrict__ ts,
                 const float* __restrict__ te,
                 const float* __restrict__ sg,
                 float* __restrict__ out,
                 int S, int n_rays)
{
    __shared__ float sm[256];
    const int tid = threadIdx.x;
    const int r = blockIdx.x * 256 + tid;
    const int R = (S + 15) >> 4;

    for (int j = r; j < n_rays; j += gridDim.x * blockDim.x)
        reinterpret_cast<float4*>(out)[j] = make_float4(0.f, 0.f, 0.f, 0.f);

    float acc = 0.0f;
    if (r < R) {
        const int base = r << 4;
        if (base + 16 <= S) {
            const float4* ts4 = reinterpret_cast<const float4*>(ts + base);
            const float4* te4 = reinterpret_cast<const float4*>(te + base);
            const float4* sg4 = reinterpret_cast<const float4*>(sg + base);
            float4*       sd4 = reinterpret_cast<float4*>(g_sdt + base);
            #pragma unroll
            for (int q = 0; q < 4; q++) {
                const float4 a = ts4[q], b = te4[q], s = sg4[q];
                float4 v;
                v.x = __fmul_rn(s.x, __fsub_rn(b.x, a.x));
                v.y = __fmul_rn(s.y, __fsub_rn(b.y, a.y));
                v.z = __fmul_rn(s.z, __fsub_rn(b.z, a.z));
                v.w = __fmul_rn(s.w, __fsub_rn(b.w, a.w));
                sd4[q] = v;
                acc = __fadd_rn(acc, v.x);   // exact fold-left order preserved
                acc = __fadd_rn(acc, v.y);
                acc = __fadd_rn(acc, v.z);
                acc = __fadd_rn(acc, v.w);
            }
        } else {
            const int lim = S - base;
            for (int k = 0; k < lim; k++) {
                const int i = base + k;
                const float v = __fmul_rn(sg[i], __fsub_rn(te[i], ts[i]));
                g_sdt[i] = v;
                acc = __fadd_rn(acc, v);
            }
        }
        g_l1[r] = acc;
    }

    sm[tid] = acc;               // acc==0 for inactive threads (inert: sdt>=0)
    __syncthreads();
    if (tid < 16) {
        const int rowb = tid << 4;
        float a2 = 0.0f;
        #pragma unroll
        for (int k = 0; k < 16; k++)
            a2 = __fadd_rn(a2, sm[rowb + k]);
        g_l2[blockIdx.x * 16 + tid] = a2;
    }
}

// ---------------------------------------------------------------------------
// K3: single-CTA exact radix-16 scan: out = cum(in), n <= 16384.
// ---------------------------------------------------------------------------
__device__ __forceinline__ void seq_scan(float* a, int n) {
    float acc = 0.0f;
    for (int i = 0; i < n; i++) { acc = __fadd_rn(acc, a[i]); a[i] = acc; }
}

__global__ __launch_bounds__(1024)
void k3_midscan(const float* __restrict__ in, float* __restrict__ out, int n)
{
    __shared__ float b1[1024], b2[64], b3[4];
    const int tid = threadIdx.x;

    if (n <= 16) {
        if (tid == 0) {
            float acc = 0.0f;
            for (int i = 0; i < n; i++) { acc = __fadd_rn(acc, in[i]); out[i] = acc; }
        }
        return;
    }

    const int m1 = (n + 15) >> 4;
    for (int q = tid; q < m1; q += 1024) {
        const int base = q << 4, lim = min(16, n - base);
        float acc = 0.0f;
        if (lim == 16) {
            const float4* in4 = reinterpret_cast<const float4*>(in + base);
            #pragma unroll
            for (int t = 0; t < 4; t++) {
                const float4 v = in4[t];
                acc = __fadd_rn(acc, v.x); acc = __fadd_rn(acc, v.y);
                acc = __fadd_rn(acc, v.z); acc = __fadd_rn(acc, v.w);
            }
        } else {
            for (int k = 0; k < lim; k++) acc = __fadd_rn(acc, in[base + k]);
        }
        b1[q] = acc;
    }
    __syncthreads();

    if (m1 <= 16) {
        if (tid == 0) seq_scan(b1, m1);
        __syncthreads();
    } else {
        const int m2 = (m1 + 15) >> 4;
        if (tid < m2) {
            const int base = tid << 4, lim = min(16, m1 - base);
            float acc = 0.0f;
            for (int k = 0; k < lim; k++) acc = __fadd_rn(acc, b1[base + k]);
            b2[tid] = acc;
        }
        __syncthreads();
        if (m2 <= 16) {
            if (tid == 0) seq_scan(b2, m2);
            __syncthreads();
        } else {
            const int m3 = (m2 + 15) >> 4;      // <= 4
            if (tid < m3) {
                const int base = tid << 4, lim = min(16, m2 - base);
                float acc = 0.0f;
                for (int k = 0; k < lim; k++) acc = __fadd_rn(acc, b2[base + k]);
                b3[tid] = acc;
            }
            __syncthreads();
            if (tid == 0) seq_scan(b3, m3);
            __syncthreads();
            if (tid < m3) {
                const int base = tid << 4, lim = min(16, m2 - base);
                float acc = 0.0f;
                const float p = (tid > 0) ? b3[tid - 1] : 0.0f;
                for (int k = 0; k < lim; k++) {
                    acc = __fadd_rn(acc, b2[base + k]);
                    b2[base + k] = (tid == 0) ? acc : __fadd_rn(acc, p);
                }
            }
            __syncthreads();
        }
        if (tid < m2) {
            const int base = tid << 4, lim = min(16, m1 - base);
            float acc = 0.0f;
            const float p = (tid > 0) ? b2[tid - 1] : 0.0f;
            for (int k = 0; k < lim; k++) {
                acc = __fadd_rn(acc, b1[base + k]);
                b1[base + k] = (tid == 0) ? acc : __fadd_rn(acc, p);
            }
        }
        __syncthreads();
    }
    for (int q = tid; q < m1; q += 1024) {
        const int base = q << 4, lim = min(16, n - base);
        float acc = 0.0f;
        const float p = (q > 0) ? b1[q - 1] : 0.0f;
        for (int k = 0; k < lim; k++) {
            acc = __fadd_rn(acc, in[base + k]);
            out[base + k] = (q == 0) ? acc : __fadd_rn(acc, p);
        }
    }
}

// ---------------------------------------------------------------------------
// K4b: l1s[r] = foldleft(l1[16q .. r]) (+ l2s[q-1] if q>0) — exact k4
// bracketing; small kernel, smem fold, no spills.
// ---------------------------------------------------------------------------
__global__ __launch_bounds__(256)
void k4b_scan_l1(int n1)
{
    __shared__ float sm[256];
    const int tid = threadIdx.x;
    const int r = blockIdx.x * 256 + tid;
    sm[tid] = (r < n1) ? g_l1[r] : 0.0f;
    __syncthreads();
    if (r >= n1) return;
    const int q = r >> 4;
    const int j = r & 15;
    const int rowlocal = tid & ~15;
    float acc = 0.0f;
    for (int k = 0; k <= j; k++)
        acc = __fadd_rn(acc, sm[rowlocal + k]);
    g_l1s[r] = (q == 0) ? acc : __fadd_rn(acc, __ldg(g_l2s + q - 1));
}

// ---------------------------------------------------------------------------
// K5: final downsweep — spill-free named-register groups, prefix p = one
// coalesced l1s[r-1] load. Stores excl = fsub(cv, sd) + per-ray e_lead.
// ---------------------------------------------------------------------------
__device__ __forceinline__ void k5_group(const float4 s, const int4 d,
                                         const bool r0, const float p,
                                         float& acc, int& prev, float4& ev)
{
    float4 cv;
    acc = __fadd_rn(acc, s.x); cv.x = r0 ? acc : __fadd_rn(acc, p);
    acc = __fadd_rn(acc, s.y); cv.y = r0 ? acc : __fadd_rn(acc, p);
    acc = __fadd_rn(acc, s.z); cv.z = r0 ? acc : __fadd_rn(acc, p);
    acc = __fadd_rn(acc, s.w); cv.w = r0 ? acc : __fadd_rn(acc, p);

    ev.x = __fsub_rn(cv.x, s.x);
    ev.y = __fsub_rn(cv.y, s.y);
    ev.z = __fsub_rn(cv.z, s.z);
    ev.w = __fsub_rn(cv.w, s.w);

    if (d.x != prev) g_elead[d.x] = ev.x;
    prev = d.x;
    if (d.y != prev) g_elead[d.y] = ev.y;
    prev = d.y;
    if (d.z != prev) g_elead[d.z] = ev.z;
    prev = d.z;
    if (d.w != prev) g_elead[d.w] = ev.w;
    prev = d.w;
}

__global__ __launch_bounds__(256)
void k5_down0_bounds(const int* __restrict__ idx, int S)
{
    const int r = blockIdx.x * blockDim.x + threadIdx.x;
    const int R = (S + 15) >> 4;
    if (r >= R) return;
    const int base = r << 4;
    const int lim  = min(16, S - base);

    const float p = (r > 0) ? __ldg(g_l1s + r - 1) : 0.0f;
    int prev = (base > 0) ? __ldg(idx + base - 1) : -1;
    const bool r0 = (r == 0);

    if (lim == 16) {
        const float4* sd4 = reinterpret_cast<const float4*>(g_sdt + base);
        const int4*   id4 = reinterpret_cast<const int4*>(idx + base);
        const float4 s0 = sd4[0], s1 = sd4[1], s2 = sd4[2], s3 = sd4[3];
        const int4   d0 = id4[0], d1 = id4[1], d2 = id4[2], d3 = id4[3];
        float4* e4 = reinterpret_cast<float4*>(g_e + base);

        float acc = 0.0f;
        float4 ev;
        k5_group(s0, d0, r0, p, acc, prev, ev); e4[0] = ev;
        k5_group(s1, d1, r0, p, acc, prev, ev); e4[1] = ev;
        k5_group(s2, d2, r0, p, acc, prev, ev); e4[2] = ev;
        k5_group(s3, d3, r0, p, acc, prev, ev); e4[3] = ev;
    } else {
        float acc = 0.0f;
        for (int k = 0; k < lim; k++) {
            const int i = base + k;
            const float s = g_sdt[i];
            acc = __fadd_rn(acc, s);
            const float c = r0 ? acc : __fadd_rn(acc, p);
            const float e = __fsub_rn(c, s);
            g_e[i] = e;
            const int cur = idx[i];
            if (cur != prev) g_elead[cur] = e;
            prev = cur;
        }
    }
}

// ---------------------------------------------------------------------------
// K6: pack-centric render. 4 samples/thread, vectorized loads, sequential
// run-walk + segmented Kogge-Stone over pack aggregates, atomicAdd flushes.
// ---------------------------------------------------------------------------
__device__ __forceinline__ void k6_flush(float* __restrict__ out, int ray,
                                         float o, float r, float g, float b)
{
    if (ray >= 0) {
        float* p = out + 4l * ray;
        atomicAdd(p + 0, o);
        atomicAdd(p + 1, r);
        atomicAdd(p + 2, g);
        atomicAdd(p + 3, b);
    }
}

__global__ __launch_bounds__(256)
void k6_render_pack(const int* __restrict__ idx,
                    const float* __restrict__ hdr,
                    float*       __restrict__ out,
                    int S)
{
    const int t    = blockIdx.x * 256 + threadIdx.x;
    const int lane = threadIdx.x & 31;
    const int i0   = t << 2;

    int4 rv = make_int4(-1, -1, -1, -1);
    // per-sample contributions (opacity, r, g, b)
    float o0=0,r0=0,g0=0,b0=0, o1=0,r1=0,g1=0,b1=0;
    float o2=0,r2=0,g2=0,b2=0, o3=0,r3=0,g3=0,b3=0;

    if (i0 + 4 <= S) {
        rv = __ldg(reinterpret_cast<const int4*>(idx) + t);
        const float4 s4 = __ldg(reinterpret_cast<const float4*>(g_sdt) + t);
        const float4 e4 = __ldg(reinterpret_cast<const float4*>(g_e) + t);
        const float4 h0 = __ldg(reinterpret_cast<const float4*>(hdr) + 3l*t + 0);
        const float4 h1 = __ldg(reinterpret_cast<const float4*>(hdr) + 3l*t + 1);
        const float4 h2 = __ldg(reinterpret_cast<const float4*>(hdr) + 3l*t + 2);

        const float el0 = __ldg(g_elead + rv.x);
        const float el1 = (rv.y == rv.x) ? el0 : __ldg(g_elead + rv.y);
        const float el2 = (rv.z == rv.y) ? el1 : __ldg(g_elead + rv.z);
        const float el3 = (rv.w == rv.z) ? el2 : __ldg(g_elead + rv.w);

        // byte-exact weight sequence per sample
        float w;
        w = __fmul_rn(expf(-__fsub_rn(e4.x, el0)), 1.0f - expf(-s4.x));
        o0 = w; r0 = w * h0.x; g0 = w * h0.y; b0 = w * h0.z;
        w = __fmul_rn(expf(-__fsub_rn(e4.y, el1)), 1.0f - expf(-s4.y));
        o1 = w; r1 = w * h0.w; g1 = w * h1.x; b1 = w * h1.y;
        w = __fmul_rn(expf(-__fsub_rn(e4.z, el2)), 1.0f - expf(-s4.z));
        o2 = w; r2 = w * h1.z; g2 = w * h1.w; b2 = w * h2.x;
        w = __fmul_rn(expf(-__fsub_rn(e4.w, el3)), 1.0f - expf(-s4.w));
        o3 = w; r3 = w * h2.y; g3 = w * h2.z; b3 = w * h2.w;
    } else if (i0 < S) {
        // tail: scalar guarded loads
        int rr[4] = {-1, -1, -1, -1};
        for (int k = 0; k < 4; k++) {
            const int i = i0 + k;
            if (i < S) {
                const int ray = __ldg(idx + i);
                rr[k] = ray;
                const float s  = __ldg(g_sdt + i);
                const float ei = __ldg(g_e + i);
                const float el = __ldg(g_elead + ray);
                const float w  = __fmul_rn(expf(-__fsub_rn(ei, el)),
                                           1.0f - expf(-s));
                const long h = 3l * i;
                const float hr = __ldg(hdr + h + 0);
                const float hg = __ldg(hdr + h + 1);
                const float hb = __ldg(hdr + h + 2);
                if (k == 0)      { o0=w; r0=w*hr; g0=w*hg; b0=w*hb; }
                else if (k == 1) { o1=w; r1=w*hr; g1=w*hg; b1=w*hb; }
                else if (k == 2) { o2=w; r2=w*hr; g2=w*hg; b2=w*hb; }
                else             { o3=w; r3=w*hr; g3=w*hg; b3=w*hb; }
            }
        }
        rv = make_int4(rr[0], rr[1], rr[2], rr[3]);
    }

    // neighbor info (all lanes participate; edges handled explicitly)
    const int prev_last = __shfl_up_sync(0xffffffffu, rv.w, 1);
    const int nxt_first = __shfl_down_sync(0xffffffffu, rv.x, 1);
    const bool pfx_open = (lane > 0) && (rv.x >= 0) && (rv.x == prev_last);

    // sequential run walk over the 4 samples
    int   cur = rv.x;
    float ao = o0, ar = r0, ag = g0, ab = b0;
    bool  firstRun = true;
    bool  pending = false;
    int   pray = -1;
    float po = 0, pr = 0, pg = 0, pb = 0;

    #pragma unroll
    for (int k = 1; k < 4; k++) {
        const int   kr = (k == 1) ? rv.y : (k == 2) ? rv.z : rv.w;
        const float vo = (k == 1) ? o1 : (k == 2) ? o2 : o3;
        const float vr = (k == 1) ? r1 : (k == 2) ? r2 : r3;
        const float vg = (k == 1) ? g1 : (k == 2) ? g2 : g3;
        const float vb = (k == 1) ? b1 : (k == 2) ? b2 : b3;
        if (kr == cur) {
            ao += vo; ar += vr; ag += vg; ab += vb;
        } else {
            if (firstRun && pfx_open) {
                pending = true; pray = cur; po = ao; pr = ar; pg = ag; pb = ab;
            } else {
                k6_flush(out, cur, ao, ar, ag, ab);
            }
            firstRun = false;
            cur = kr; ao = vo; ar = vr; ag = vg; ab = vb;
        }
    }

    // segmented Kogge-Stone over pack aggregates
    float So = ao, Sr = ar, Sg = ag, Sb = ab;
    unsigned F = (firstRun && pfx_open) ? 0u : 1u;
    #pragma unroll
    for (int d = 1; d < 32; d <<= 1) {
        const float    xo = __shfl_up_sync(0xffffffffu, So, d);
        const float    xr = __shfl_up_sync(0xffffffffu, Sr, d);
        const float    xg = __shfl_up_sync(0xffffffffu, Sg, d);
        const float    xb = __shfl_up_sync(0xffffffffu, Sb, d);
        const unsigned xF = __shfl_up_sync(0xffffffffu, F,  d);
        if (lane >= d && !F) {
            So += xo; Sr += xr; Sg += xg; Sb += xb;
            F |= xF;
        }
    }

    // prefix-run flush (run ended inside pack, connects left):
    const float co = __shfl_up_sync(0xffffffffu, So, 1);
    const float cr = __shfl_up_sync(0xffffffffu, Sr, 1);
    const float cg = __shfl_up_sync(0xffffffffu, Sg, 1);
    const float cb = __shfl_up_sync(0xffffffffu, Sb, 1);
    if (pending)
        k6_flush(out, pray, co + po, cr + pr, cg + pg, cb + pb);

    // trailing-run flush: last pack of the run within this warp
    const bool segend = (lane == 31) || (nxt_first != rv.w);
    if (segend)
        k6_flush(out, cur, So, Sr, Sg, Sb);
}

// ---------------------------------------------------------------------------
extern "C" void kernel_launch(void* const* d_in, const int* in_sizes, int n_in,
                              void* d_out, int out_size)
{
    const float* t_starts    = (const float*)d_in[0];
    const float* t_ends      = (const float*)d_in[1];
    const float* sigmas      = (const float*)d_in[2];
    const float* hdr         = (const float*)d_in[3];
    const int*   ray_indices = (const int*)  d_in[4];
    float*       out         = (float*)d_out;

    const int S      = in_sizes[0];
    const int n_rays = out_size / 4;

    const int n1 = (S + 15) >> 4;
    const int n2 = (n1 + 15) >> 4;

    float *l2 = nullptr, *l2s = nullptr;
    cudaGetSymbolAddress((void**)&l2,  g_l2);
    cudaGetSymbolAddress((void**)&l2s, g_l2s);

    const int T = 256;
    const int g1 = (n1 + T - 1) / T;

    k1_sdt_fold<<<g1, T>>>(t_starts, t_ends, sigmas, out, S, n_rays);
    k3_midscan<<<1, 1024>>>(l2, l2s, n2);
    k4b_scan_l1<<<g1, T>>>(n1);
    k5_down0_bounds<<<g1, T>>>(ray_indices, S);

    const int packs = (S + 3) >> 2;
    const int g6 = (packs + T - 1) / T;
    k6_render_pack<<<g6, T>>>(ray_indices, hdr, out, S);
}